// round 16
// baseline (speedup 1.0000x reference)
#include <cuda_runtime.h>
#include <cuda_fp16.h>
#include <math.h>

// ---------------------------------------------------------------------------
// MoE Router via 3xFP16-split mma.sync m16n8k16 GEMM, warp-specialized:
// 4 producer warps (LDG + split-convert + STS, 3-stage ring) feed 8 consumer
// warps (ldmatrix + MMA). Running accumulator lives in SMEM (folded once per
// chunk) freeing ~32 registers for ptxas software pipelining. Hi-chain folded
// per 64-K chunk; lo-chain segmented over 8 chunks in HMMA registers.
// logits = X[16384,2048] @ W[64,2048]^T + b ; softmax; top-2; renorm; one-hot.
// Output (fp32 flattened): logits | weights | selected(as float) | mask
// ---------------------------------------------------------------------------

#define T_TOKENS 16384
#define K_DIM    2048
#define E_DIM    64
#define BLK_T    128
#define KC       64                 // K elements per chunk (8 k8-blocks)
#define NCHUNK   (K_DIM / KC)       // 32
#define THREADS  384                // 8 consumer + 4 producer warps
#define NSTAGE   3

#define OFF_W    (T_TOKENS * E_DIM)
#define OFF_SEL  (OFF_W + T_TOKENS * 2)
#define OFF_MASK (OFF_SEL + T_TOKENS * 2)

// ---- SMEM stage: Ah | Al | Bh | Bl (k8-block layout, 16B pad/block)
#define ABLK   2064                 // 128 rows * 16B + 16B pad
#define BBLK   1040                 // 64 rows * 16B + 16B pad
#define AHo    0
#define ALo    (8 * ABLK)           // 16512
#define BHo    (2 * 8 * ABLK)       // 33024
#define BLo    (BHo + 8 * BBLK)     // 41344
#define BUFSZ  (BHo + 2 * 8 * BBLK) // 49664
#define ACCO   (NSTAGE * BUFSZ)     // 148992: 128 x 68 fp32 accumulator
#define ACC_STR 68                  // row stride (16B-aligned rows, low conflicts)
#define SBIAS  (ACCO + 128 * ACC_STR * 4)   // 183808
#define SMEM_TOTAL (SBIAS + 256)    // 184064

#define LO_SCALE   2048.0f
#define LO_UNSCALE 4.8828125e-4f    // 1/2048

static __device__ unsigned g_Wp[E_DIM * K_DIM];   // packed: lo16=h, hi16=l*2048

__device__ __forceinline__ void mma16(float* c, const unsigned* a, const unsigned* b) {
    asm("mma.sync.aligned.m16n8k16.row.col.f32.f16.f16.f32 "
        "{%0,%1,%2,%3}, {%4,%5,%6,%7}, {%8,%9}, {%0,%1,%2,%3};"
        : "+f"(c[0]), "+f"(c[1]), "+f"(c[2]), "+f"(c[3])
        : "r"(a[0]), "r"(a[1]), "r"(a[2]), "r"(a[3]), "r"(b[0]), "r"(b[1]));
}
__device__ __forceinline__ void mma16z(float* c, const unsigned* a, const unsigned* b) {
    asm("mma.sync.aligned.m16n8k16.row.col.f32.f16.f16.f32 "
        "{%0,%1,%2,%3}, {%4,%5,%6,%7}, {%8,%9}, {%10,%10,%10,%10};"
        : "=f"(c[0]), "=f"(c[1]), "=f"(c[2]), "=f"(c[3])
        : "r"(a[0]), "r"(a[1]), "r"(a[2]), "r"(a[3]), "r"(b[0]), "r"(b[1]),
          "f"(0.0f));
}
__device__ __forceinline__ void ldsm4(unsigned& r0, unsigned& r1,
                                      unsigned& r2, unsigned& r3, unsigned a) {
    asm volatile("ldmatrix.sync.aligned.m8n8.x4.shared.b16 {%0,%1,%2,%3}, [%4];"
                 : "=r"(r0), "=r"(r1), "=r"(r2), "=r"(r3) : "r"(a));
}
__device__ __forceinline__ void sts64(unsigned p, unsigned a, unsigned b) {
    asm volatile("st.shared.v2.b32 [%0], {%1,%2};"
                 :: "r"(p), "r"(a), "r"(b) : "memory");
}
__device__ __forceinline__ unsigned pack_h2(float x, float y) {
    __half2 h = __halves2half2(__float2half_rn(x), __float2half_rn(y));
    return *(unsigned*)&h;
}
__device__ __forceinline__ unsigned smem_u32(const void* p) {
    unsigned a;
    asm("{ .reg .u64 t; cvta.to.shared.u64 t, %1; cvt.u32.u64 %0, t; }"
        : "=r"(a) : "l"(p));
    return a;
}
__device__ __forceinline__ void bar_sync(int id) {
    asm volatile("bar.sync %0, %1;" :: "r"(id), "n"(THREADS) : "memory");
}
__device__ __forceinline__ void bar_arrive(int id) {
    asm volatile("bar.arrive %0, %1;" :: "r"(id), "n"(THREADS) : "memory");
}

// ---------------- W split pre-kernel ----------------
__global__ void wsplit_kernel(const float* __restrict__ W) {
    int i = blockIdx.x * 256 + threadIdx.x;
    float w = W[i];
    __half h = __float2half_rn(w);
    __half l = __float2half_rn((w - __half2float(h)) * LO_SCALE);
    g_Wp[i] = (unsigned)__half_as_ushort(h) | ((unsigned)__half_as_ushort(l) << 16);
}

// ---------------- main kernel ----------------
__global__ __launch_bounds__(THREADS, 1)
void moe_mma_kernel(const float* __restrict__ X,
                    const float* __restrict__ bias,
                    float* __restrict__ out)
{
    extern __shared__ char sm[];
    const unsigned smb = smem_u32(sm);
    const int tid  = threadIdx.x;
    const int wid  = tid >> 5;
    const int lane = tid & 31;
    const int t0   = blockIdx.x * BLK_T;

    // zero the smem accumulator (all threads, before any barrier)
    {
        float* accp = (float*)(sm + ACCO);
        for (int i = tid; i < 128 * ACC_STR; i += THREADS) accp[i] = 0.f;
    }
    if (tid < E_DIM) ((float*)(sm + SBIAS))[tid] = bias[tid];

    if (wid >= 8) {
        // ================= PRODUCER (warps 8-11, 128 threads) =================
        const int ptid = tid - 256;
        const int prow = ptid >> 4;          // 0..7
        const int pj   = ptid & 15;          // float4/uint4 column 0..15
        const float4* X4  = (const float4*)X;
        const uint4*  Wp4 = (const uint4*)g_Wp;

        float4 xr[16];
        uint4  wr[8];

#define P_LDGX(C) do {                                                        \
    _Pragma("unroll")                                                         \
    for (int q = 0; q < 16; ++q)                                              \
        xr[q] = X4[(size_t)(t0 + prow + 8 * q) * (K_DIM / 4) + (C) * 16 + pj];\
    } while (0)
#define P_LDGW(C) do {                                                        \
    _Pragma("unroll")                                                         \
    for (int q = 0; q < 8; ++q)                                               \
        wr[q] = Wp4[(size_t)(prow + 8 * q) * (K_DIM / 4) + (C) * 16 + pj];    \
    } while (0)

        P_LDGX(0); P_LDGW(0);

        int s = 0;
        for (int c = 0; c < NCHUNK; ++c) {
            if (c >= NSTAGE) bar_sync(4 + s);          // wait stage empty
            const unsigned bb = smb + (unsigned)s * BUFSZ;
            const unsigned offA = (pj >> 1) * ABLK + (pj & 1) * 8;
            const unsigned offB = (pj >> 1) * BBLK + (pj & 1) * 8;
#pragma unroll
            for (int q = 0; q < 16; ++q) {
                const int row = prow + 8 * q;
                float4 v = xr[q];
                float hx = __half2float(__float2half_rn(v.x));
                float hy = __half2float(__float2half_rn(v.y));
                float hz = __half2float(__float2half_rn(v.z));
                float hw = __half2float(__float2half_rn(v.w));
                sts64(bb + AHo + offA + row * 16,
                      pack_h2(v.x, v.y), pack_h2(v.z, v.w));
                sts64(bb + ALo + offA + row * 16,
                      pack_h2((v.x - hx) * LO_SCALE, (v.y - hy) * LO_SCALE),
                      pack_h2((v.z - hz) * LO_SCALE, (v.w - hw) * LO_SCALE));
            }
#pragma unroll
            for (int q = 0; q < 8; ++q) {
                const int row = prow + 8 * q;
                uint4 u = wr[q];
                sts64(bb + BHo + offB + row * 16,
                      __byte_perm(u.x, u.y, 0x5410), __byte_perm(u.z, u.w, 0x5410));
                sts64(bb + BLo + offB + row * 16,
                      __byte_perm(u.x, u.y, 0x7632), __byte_perm(u.z, u.w, 0x7632));
            }
            if (c + 1 < NCHUNK) { P_LDGX(c + 1); P_LDGW(c + 1); }
            bar_sync(1 + s);                           // publish stage full
            s = (s == NSTAGE - 1) ? 0 : s + 1;
        }
    } else {
        // ================= CONSUMER (warps 0-7, 256 threads) =================
        const int g  = lane >> 2;
        const int tg = lane & 3;
        const int RB = (wid >> 1) * 32;   // 4 row groups
        const int CB = (wid & 1) * 32;    // 2 col groups

        const unsigned blkA = (unsigned)(lane >> 4) * ABLK + (unsigned)(lane & 15) * 16;
        const unsigned blkB = (unsigned)(lane >> 4) * BBLK + (unsigned)(lane & 15) * 16;
        const unsigned aBase0 = smb + AHo + blkA + (unsigned)RB * 16;
        const unsigned bBase0 = smb + BHo + blkB + (unsigned)CB * 16;

        float* accp = (float*)(sm + ACCO);
        float accL[2][4][4];    // lo chain, HMMA-resident, folded every 8 chunks

        int s = 0;
        for (int c = 0; c < NCHUNK; ++c) {
            bar_sync(1 + s);                           // wait stage full
            const unsigned aB = aBase0 + (unsigned)s * BUFSZ;
            const unsigned bB = bBase0 + (unsigned)s * BUFSZ;
            float cah[2][4][4];
            const bool zL = ((c & 7) == 0);            // new lo segment
#pragma unroll
            for (int st = 0; st < 4; ++st) {           // 4 k16 steps
                unsigned ah[2][4], al[2][4], bh[4][2], bl[4][2];
                const unsigned as  = aB + (2 * st) * ABLK;
                const unsigned bs_ = bB + (2 * st) * BBLK;
#pragma unroll
                for (int mi = 0; mi < 2; ++mi) {
                    ldsm4(ah[mi][0], ah[mi][1], ah[mi][2], ah[mi][3],
                          as + mi * 256);
                    ldsm4(al[mi][0], al[mi][1], al[mi][2], al[mi][3],
                          as + ALo + mi * 256);
                }
#pragma unroll
                for (int np = 0; np < 2; ++np) {
                    unsigned r0, r1, r2, r3;
                    ldsm4(r0, r1, r2, r3, bs_ + np * 256);
                    bh[2 * np][0] = r0; bh[2 * np][1] = r2;
                    bh[2 * np + 1][0] = r1; bh[2 * np + 1][1] = r3;
                    ldsm4(r0, r1, r2, r3, bs_ + (BLo - BHo) + np * 256);
                    bl[2 * np][0] = r0; bl[2 * np][1] = r2;
                    bl[2 * np + 1][0] = r1; bl[2 * np + 1][1] = r3;
                }
                if (st == 3 && c + NSTAGE < NCHUNK)
                    bar_arrive(4 + s);                 // early stage release
                // hi chain (chunk-scoped)
#pragma unroll
                for (int mi = 0; mi < 2; ++mi)
#pragma unroll
                    for (int ni = 0; ni < 4; ++ni) {
                        if (st == 0) mma16z(cah[mi][ni], ah[mi], bh[ni]);
                        else         mma16 (cah[mi][ni], ah[mi], bh[ni]);
                    }
                // lo chain (segment-scoped, runs long in HMMA)
#pragma unroll
                for (int mi = 0; mi < 2; ++mi)
#pragma unroll
                    for (int ni = 0; ni < 4; ++ni) {
                        if (zL && st == 0) mma16z(accL[mi][ni], ah[mi], bl[ni]);
                        else               mma16 (accL[mi][ni], ah[mi], bl[ni]);
                        mma16(accL[mi][ni], al[mi], bh[ni]);
                    }
            }
            // fold hi chunk partials into SMEM accumulator (RN fp32 adds);
            // at segment end also fold the lo chain (matches R15 op order).
            const bool segEnd = ((c & 7) == 7);
#pragma unroll
            for (int mi = 0; mi < 2; ++mi) {
                const int r0 = RB + 16 * mi + g;
#pragma unroll
                for (int ni = 0; ni < 4; ++ni) {
                    const int col = CB + 8 * ni + 2 * tg;
                    float2* p0 = (float2*)(accp + r0 * ACC_STR + col);
                    float2* p1 = (float2*)(accp + (r0 + 8) * ACC_STR + col);
                    float2 v0 = *p0, v1 = *p1;
                    v0.x += cah[mi][ni][0]; v0.y += cah[mi][ni][1];
                    v1.x += cah[mi][ni][2]; v1.y += cah[mi][ni][3];
                    if (segEnd) {
                        v0.x = fmaf(accL[mi][ni][0], LO_UNSCALE, v0.x);
                        v0.y = fmaf(accL[mi][ni][1], LO_UNSCALE, v0.y);
                        v1.x = fmaf(accL[mi][ni][2], LO_UNSCALE, v1.x);
                        v1.y = fmaf(accL[mi][ni][3], LO_UNSCALE, v1.y);
                    }
                    *p0 = v0; *p1 = v1;
                }
            }
            s = (s == NSTAGE - 1) ? 0 : s + 1;
        }
    }

    __syncthreads();

    // -------- fused router + logits writeback: one thread per token --------
    if (tid < BLK_T) {
        const float* bs  = (const float*)(sm + SBIAS);
        const float* row = (const float*)(sm + ACCO) + tid * ACC_STR;
        const int tok = t0 + tid;
        float4* lg = (float4*)(out + (size_t)tok * E_DIM);

        float b1 = -1e30f, b2 = -1e30f;
        int   i1 = 0,      i2 = 0;
#pragma unroll
        for (int jq = 0; jq < 16; ++jq) {
            float4 v = *(const float4*)(row + 4 * jq);
            const float4 bb = *(const float4*)(bs + 4 * jq);
            v.x += bb.x; v.y += bb.y; v.z += bb.z; v.w += bb.w;
            lg[jq] = v;
            const int e = 4 * jq;
            if (v.x > b1)      { b2 = b1; i2 = i1; b1 = v.x; i1 = e; }
            else if (v.x > b2) { b2 = v.x; i2 = e; }
            if (v.y > b1)      { b2 = b1; i2 = i1; b1 = v.y; i1 = e + 1; }
            else if (v.y > b2) { b2 = v.y; i2 = e + 1; }
            if (v.z > b1)      { b2 = b1; i2 = i1; b1 = v.z; i1 = e + 2; }
            else if (v.z > b2) { b2 = v.z; i2 = e + 2; }
            if (v.w > b1)      { b2 = b1; i2 = i1; b1 = v.w; i1 = e + 3; }
            else if (v.w > b2) { b2 = v.w; i2 = e + 3; }
        }

        const float e2 = expf(b2 - b1);        // softmax denom cancels in renorm
        const float w1 = 1.0f / (1.0f + e2);
        out[OFF_W + 2 * tok]     = w1;
        out[OFF_W + 2 * tok + 1] = e2 * w1;
        out[OFF_SEL + 2 * tok]     = (float)i1;
        out[OFF_SEL + 2 * tok + 1] = (float)i2;

        float4* m4 = (float4*)(out + OFF_MASK + (size_t)tok * 128);
        const float4 z = make_float4(0.f, 0.f, 0.f, 0.f);
#pragma unroll
        for (int q = 0; q < 32; ++q) m4[q] = z;
        out[OFF_MASK + (size_t)tok * 128 + i1]      = 1.0f;
        out[OFF_MASK + (size_t)tok * 128 + 64 + i2] = 1.0f;
    }
}

extern "C" void kernel_launch(void* const* d_in, const int* in_sizes, int n_in,
                              void* d_out, int out_size)
{
    const float* X = (const float*)d_in[0];
    const float* W = (const float*)d_in[1];
    const float* b = (const float*)d_in[2];
    float* out = (float*)d_out;

    cudaFuncSetAttribute(moe_mma_kernel,
                         cudaFuncAttributeMaxDynamicSharedMemorySize, SMEM_TOTAL);

    wsplit_kernel<<<(E_DIM * K_DIM) / 256, 256>>>(W);
    moe_mma_kernel<<<T_TOKENS / BLK_T, THREADS, SMEM_TOTAL>>>(X, b, out);
}

// round 17
// speedup vs baseline: 1.2595x; 1.2595x over previous
#include <cuda_runtime.h>
#include <cuda_fp16.h>
#include <math.h>

// ---------------------------------------------------------------------------
// MoE Router via 3xFP16-split mma.sync m16n8k16 GEMM, warp-specialized:
// 4 producer warps (LDG + split-convert + STS) feed 8 consumer warps
// (ldmatrix + MMA). Ring of 2 BIG stages (128 K each = two 64-K sub-chunks).
// W is split fp32->fp16 hi/lo IN-KERNEL by the producers (no pre-kernel, no
// extra graph launch). Hi-chain folded per 64-K chunk; lo-chain segmented
// over 8 chunks in HMMA registers.
// logits = X[16384,2048] @ W[64,2048]^T + b ; softmax; top-2; renorm; one-hot.
// Output (fp32 flattened): logits | weights | selected(as float) | mask
// ---------------------------------------------------------------------------

#define T_TOKENS 16384
#define K_DIM    2048
#define E_DIM    64
#define BLK_T    128
#define KC       64                 // K elements per numeric sub-chunk
#define NCHUNK   (K_DIM / KC)       // 32 sub-chunks
#define NSTG     (NCHUNK / 2)       // 16 big-stage iterations
#define THREADS  384                // 8 consumer + 4 producer warps
#define NSTAGE   2                  // ring depth in BIG stages (=4 sub-buffers)

#define OFF_W    (T_TOKENS * E_DIM)
#define OFF_SEL  (OFF_W + T_TOKENS * 2)
#define OFF_MASK (OFF_SEL + T_TOKENS * 2)

// ---- SMEM sub-buffer: Ah | Al | Bh | Bl (k8-block layout, 16B pad/block)
#define ABLK   2064                 // 128 rows * 16B + 16B pad
#define BBLK   1040                 // 64 rows * 16B + 16B pad
#define AHo    0
#define ALo    (8 * ABLK)           // 16512
#define BHo    (2 * 8 * ABLK)       // 33024
#define BLo    (BHo + 8 * BBLK)     // 41344
#define BUFSZ  (BHo + 2 * 8 * BBLK) // 49664 per 64-K sub-buffer
#define SBIAS  (4 * BUFSZ)          // 198656 (4 sub-buffers = 2 big stages)
#define SMEM_TOTAL (SBIAS + 256)    // 198912
// epilogue logits scratch (128 x 65 fp32 = 33280B) aliases sub-buffer 0

#define LO_SCALE   2048.0f
#define LO_UNSCALE 4.8828125e-4f    // 1/2048

__device__ __forceinline__ void mma16(float* c, const unsigned* a, const unsigned* b) {
    asm("mma.sync.aligned.m16n8k16.row.col.f32.f16.f16.f32 "
        "{%0,%1,%2,%3}, {%4,%5,%6,%7}, {%8,%9}, {%0,%1,%2,%3};"
        : "+f"(c[0]), "+f"(c[1]), "+f"(c[2]), "+f"(c[3])
        : "r"(a[0]), "r"(a[1]), "r"(a[2]), "r"(a[3]), "r"(b[0]), "r"(b[1]));
}
__device__ __forceinline__ void mma16z(float* c, const unsigned* a, const unsigned* b) {
    asm("mma.sync.aligned.m16n8k16.row.col.f32.f16.f16.f32 "
        "{%0,%1,%2,%3}, {%4,%5,%6,%7}, {%8,%9}, {%10,%10,%10,%10};"
        : "=f"(c[0]), "=f"(c[1]), "=f"(c[2]), "=f"(c[3])
        : "r"(a[0]), "r"(a[1]), "r"(a[2]), "r"(a[3]), "r"(b[0]), "r"(b[1]),
          "f"(0.0f));
}
__device__ __forceinline__ void ldsm4(unsigned& r0, unsigned& r1,
                                      unsigned& r2, unsigned& r3, unsigned a) {
    asm volatile("ldmatrix.sync.aligned.m8n8.x4.shared.b16 {%0,%1,%2,%3}, [%4];"
                 : "=r"(r0), "=r"(r1), "=r"(r2), "=r"(r3) : "r"(a));
}
__device__ __forceinline__ void sts64(unsigned p, unsigned a, unsigned b) {
    asm volatile("st.shared.v2.b32 [%0], {%1,%2};"
                 :: "r"(p), "r"(a), "r"(b) : "memory");
}
__device__ __forceinline__ unsigned pack_h2(float x, float y) {
    __half2 h = __halves2half2(__float2half_rn(x), __float2half_rn(y));
    return *(unsigned*)&h;
}
__device__ __forceinline__ unsigned smem_u32(const void* p) {
    unsigned a;
    asm("{ .reg .u64 t; cvta.to.shared.u64 t, %1; cvt.u32.u64 %0, t; }"
        : "=r"(a) : "l"(p));
    return a;
}
__device__ __forceinline__ void bar_sync(int id) {
    asm volatile("bar.sync %0, %1;" :: "r"(id), "n"(THREADS) : "memory");
}
__device__ __forceinline__ void bar_arrive(int id) {
    asm volatile("bar.arrive %0, %1;" :: "r"(id), "n"(THREADS) : "memory");
}

// ---------------- main kernel ----------------
__global__ __launch_bounds__(THREADS, 1)
void moe_mma_kernel(const float* __restrict__ X,
                    const float* __restrict__ W,
                    const float* __restrict__ bias,
                    float* __restrict__ out)
{
    extern __shared__ char sm[];
    const unsigned smb = smem_u32(sm);
    const int tid  = threadIdx.x;
    const int wid  = tid >> 5;
    const int lane = tid & 31;
    const int t0   = blockIdx.x * BLK_T;

    if (tid < E_DIM) ((float*)(sm + SBIAS))[tid] = bias[tid];

    if (wid >= 8) {
        // ================= PRODUCER (warps 8-11, 128 threads) =================
        const int ptid = tid - 256;
        const int prow = ptid >> 4;          // 0..7
        const int pj   = ptid & 15;          // float4 column 0..15
        const float4* X4 = (const float4*)X;
        const float4* W4 = (const float4*)W;

        float4 xr[16];
        float4 wr[8];

#define P_LDGX(C) do {                                                        \
    _Pragma("unroll")                                                         \
    for (int q = 0; q < 16; ++q)                                              \
        xr[q] = X4[(size_t)(t0 + prow + 8 * q) * (K_DIM / 4) + (C) * 16 + pj];\
    } while (0)
#define P_LDGW(C) do {                                                        \
    _Pragma("unroll")                                                         \
    for (int q = 0; q < 8; ++q)                                               \
        wr[q] = W4[(size_t)(prow + 8 * q) * (K_DIM / 4) + (C) * 16 + pj];     \
    } while (0)

        P_LDGX(0); P_LDGW(0);

        for (int c = 0; c < NCHUNK; ++c) {
            const int stg = c >> 1;               // big-stage index
            const int s   = stg & 1;              // ring slot
            if ((c & 1) == 0 && stg >= NSTAGE)
                bar_sync(4 + s);                  // wait big stage empty
            const unsigned bb = smb + (unsigned)(c & 3) * BUFSZ;
            const unsigned offA = (pj >> 1) * ABLK + (pj & 1) * 8;
            const unsigned offB = (pj >> 1) * BBLK + (pj & 1) * 8;
#pragma unroll
            for (int q = 0; q < 16; ++q) {
                const int row = prow + 8 * q;
                float4 v = xr[q];
                float hx = __half2float(__float2half_rn(v.x));
                float hy = __half2float(__float2half_rn(v.y));
                float hz = __half2float(__float2half_rn(v.z));
                float hw = __half2float(__float2half_rn(v.w));
                sts64(bb + AHo + offA + row * 16,
                      pack_h2(v.x, v.y), pack_h2(v.z, v.w));
                sts64(bb + ALo + offA + row * 16,
                      pack_h2((v.x - hx) * LO_SCALE, (v.y - hy) * LO_SCALE),
                      pack_h2((v.z - hz) * LO_SCALE, (v.w - hw) * LO_SCALE));
            }
#pragma unroll
            for (int q = 0; q < 8; ++q) {
                const int row = prow + 8 * q;
                float4 v = wr[q];
                float hx = __half2float(__float2half_rn(v.x));
                float hy = __half2float(__float2half_rn(v.y));
                float hz = __half2float(__float2half_rn(v.z));
                float hw = __half2float(__float2half_rn(v.w));
                sts64(bb + BHo + offB + row * 16,
                      pack_h2(v.x, v.y), pack_h2(v.z, v.w));
                sts64(bb + BLo + offB + row * 16,
                      pack_h2((v.x - hx) * LO_SCALE, (v.y - hy) * LO_SCALE),
                      pack_h2((v.z - hz) * LO_SCALE, (v.w - hw) * LO_SCALE));
            }
            if (c + 1 < NCHUNK) { P_LDGX(c + 1); P_LDGW(c + 1); }
            if (c & 1)
                bar_sync(1 + s);                  // publish big stage full
        }
    } else {
        // ================= CONSUMER (warps 0-7, 256 threads) =================
        const int g  = lane >> 2;
        const int tg = lane & 3;
        const int RB = (wid >> 1) * 32;   // 4 row groups
        const int CB = (wid & 1) * 32;    // 2 col groups

        const unsigned blkA = (unsigned)(lane >> 4) * ABLK + (unsigned)(lane & 15) * 16;
        const unsigned blkB = (unsigned)(lane >> 4) * BBLK + (unsigned)(lane & 15) * 16;
        const unsigned aBase0 = smb + AHo + blkA + (unsigned)RB * 16;
        const unsigned bBase0 = smb + BHo + blkB + (unsigned)CB * 16;

        float acc[2][4][4];     // running hi (fp32 RN folds)
        float accL[2][4][4];    // lo chain, HMMA-resident, folded every 8 chunks
#pragma unroll
        for (int mi = 0; mi < 2; ++mi)
#pragma unroll
            for (int ni = 0; ni < 4; ++ni)
#pragma unroll
                for (int q = 0; q < 4; ++q) acc[mi][ni][q] = 0.f;

        for (int stg = 0; stg < NSTG; ++stg) {
            const int s = stg & 1;
            bar_sync(1 + s);                      // wait big stage full
#pragma unroll
            for (int h = 0; h < 2; ++h) {         // two 64-K sub-chunks
                const int c = 2 * stg + h;
                const unsigned base = (unsigned)(c & 3) * BUFSZ;
                const unsigned aB = aBase0 + base;
                const unsigned bB = bBase0 + base;
                float cah[2][4][4];
                const bool zL = ((c & 7) == 0);   // new lo segment
#pragma unroll
                for (int st = 0; st < 4; ++st) {  // 4 k16 steps
                    unsigned ah[2][4], al[2][4], bh[4][2], bl[4][2];
                    const unsigned as  = aB + (2 * st) * ABLK;
                    const unsigned bs_ = bB + (2 * st) * BBLK;
#pragma unroll
                    for (int mi = 0; mi < 2; ++mi) {
                        ldsm4(ah[mi][0], ah[mi][1], ah[mi][2], ah[mi][3],
                              as + mi * 256);
                        ldsm4(al[mi][0], al[mi][1], al[mi][2], al[mi][3],
                              as + ALo + mi * 256);
                    }
#pragma unroll
                    for (int np = 0; np < 2; ++np) {
                        unsigned r0, r1, r2, r3;
                        ldsm4(r0, r1, r2, r3, bs_ + np * 256);
                        bh[2 * np][0] = r0; bh[2 * np][1] = r2;
                        bh[2 * np + 1][0] = r1; bh[2 * np + 1][1] = r3;
                        ldsm4(r0, r1, r2, r3, bs_ + (BLo - BHo) + np * 256);
                        bl[2 * np][0] = r0; bl[2 * np][1] = r2;
                        bl[2 * np + 1][0] = r1; bl[2 * np + 1][1] = r3;
                    }
                    // all smem reads of this big stage issued -> release early
                    if (h == 1 && st == 3 && stg + NSTAGE < NSTG)
                        bar_arrive(4 + s);
                    // hi chain (sub-chunk scoped)
#pragma unroll
                    for (int mi = 0; mi < 2; ++mi)
#pragma unroll
                        for (int ni = 0; ni < 4; ++ni) {
                            if (st == 0) mma16z(cah[mi][ni], ah[mi], bh[ni]);
                            else         mma16 (cah[mi][ni], ah[mi], bh[ni]);
                        }
                    // lo chain (segment-scoped, runs long in HMMA)
#pragma unroll
                    for (int mi = 0; mi < 2; ++mi)
#pragma unroll
                        for (int ni = 0; ni < 4; ++ni) {
                            if (zL && st == 0) mma16z(accL[mi][ni], ah[mi], bl[ni]);
                            else               mma16 (accL[mi][ni], ah[mi], bl[ni]);
                            mma16(accL[mi][ni], al[mi], bh[ni]);
                        }
                }
                // fold hi sub-chunk partials (RN fp32 adds)
#pragma unroll
                for (int mi = 0; mi < 2; ++mi)
#pragma unroll
                    for (int ni = 0; ni < 4; ++ni)
#pragma unroll
                        for (int q = 0; q < 4; ++q)
                            acc[mi][ni][q] += cah[mi][ni][q];
                // fold lo segment every 8 sub-chunks
                if ((c & 7) == 7) {
#pragma unroll
                    for (int mi = 0; mi < 2; ++mi)
#pragma unroll
                        for (int ni = 0; ni < 4; ++ni)
#pragma unroll
                            for (int q = 0; q < 4; ++q)
                                acc[mi][ni][q] = fmaf(accL[mi][ni][q], LO_UNSCALE,
                                                      acc[mi][ni][q]);
                }
            }
        }

        // ---------------- epilogue: logits to gmem + smem ----------------
        float* lsm = (float*)sm;                 // 128 x 65 fp32 (aliases buf0)
        const float* bs = (const float*)(sm + SBIAS);
#pragma unroll
        for (int mi = 0; mi < 2; ++mi) {
            const int r0 = RB + 16 * mi + g;
#pragma unroll
            for (int ni = 0; ni < 4; ++ni) {
                const int col = CB + 8 * ni + 2 * tg;
                const float b0 = bs[col], b1 = bs[col + 1];
                const float v00 = acc[mi][ni][0] + b0, v01 = acc[mi][ni][1] + b1;
                const float v10 = acc[mi][ni][2] + b0, v11 = acc[mi][ni][3] + b1;
                *(float2*)(out + (size_t)(t0 + r0) * E_DIM + col)     = make_float2(v00, v01);
                *(float2*)(out + (size_t)(t0 + r0 + 8) * E_DIM + col) = make_float2(v10, v11);
                lsm[r0 * 65 + col]           = v00;
                lsm[r0 * 65 + col + 1]       = v01;
                lsm[(r0 + 8) * 65 + col]     = v10;
                lsm[(r0 + 8) * 65 + col + 1] = v11;
            }
        }
    }

    __syncthreads();

    // ---------------- fused router: one thread per token ----------------
    if (tid < BLK_T) {
        float* lsm = (float*)sm;
        const int tok = t0 + tid;
        const float* row = lsm + tid * 65;
        float b1 = -1e30f, b2 = -1e30f;
        int   i1 = 0,      i2 = 0;
#pragma unroll
        for (int e = 0; e < E_DIM; ++e) {
            const float v = row[e];
            if (v > b1)      { b2 = b1; i2 = i1; b1 = v; i1 = e; }
            else if (v > b2) { b2 = v; i2 = e; }
        }
        const float e2 = expf(b2 - b1);        // softmax denom cancels in renorm
        const float w1 = 1.0f / (1.0f + e2);
        out[OFF_W + 2 * tok]     = w1;
        out[OFF_W + 2 * tok + 1] = e2 * w1;
        out[OFF_SEL + 2 * tok]     = (float)i1;
        out[OFF_SEL + 2 * tok + 1] = (float)i2;

        float4* m4 = (float4*)(out + OFF_MASK + (size_t)tok * 128);
        const float4 z = make_float4(0.f, 0.f, 0.f, 0.f);
#pragma unroll
        for (int q = 0; q < 32; ++q) m4[q] = z;
        out[OFF_MASK + (size_t)tok * 128 + i1]      = 1.0f;
        out[OFF_MASK + (size_t)tok * 128 + 64 + i2] = 1.0f;
    }
}

extern "C" void kernel_launch(void* const* d_in, const int* in_sizes, int n_in,
                              void* d_out, int out_size)
{
    const float* X = (const float*)d_in[0];
    const float* W = (const float*)d_in[1];
    const float* b = (const float*)d_in[2];
    float* out = (float*)d_out;

    cudaFuncSetAttribute(moe_mma_kernel,
                         cudaFuncAttributeMaxDynamicSharedMemorySize, SMEM_TOTAL);

    moe_mma_kernel<<<T_TOKENS / BLK_T, THREADS, SMEM_TOTAL>>>(X, W, b, out);
}